// round 9
// baseline (speedup 1.0000x reference)
#include <cuda_runtime.h>
#include <cuda_fp16.h>
#include <math.h>

// Problem constants
static constexpr int NN   = 10000;
static constexpr int EE   = 320000;
static constexpr int EN   = EE + NN;        // edges + self loops
static constexpr int IND  = 512;
static constexpr int HIDD = 128;
static constexpr int OUTD = 128;
static constexpr int HEADS = 4;
static constexpr int GC    = 64;
static constexpr int FEAT  = HEADS * GC;    // 256
static constexpr float NEG_SLOPE = 0.2f;
static constexpr int MAXDEG = 256;          // smem cache cap (deg ~ Poisson(33))
static constexpr int SCAN_BLKS = 40;        // 40*256 = 10240 >= NN

// -------- scratch (device globals: no allocation allowed) --------
__device__ float  d_h1[(size_t)NN * HIDD];
__device__ float  d_h2[(size_t)NN * OUTD];
__device__ __half d_g16[(size_t)NN * FEAT];
__device__ float  d_asrc[NN * HEADS];
__device__ float  d_adst[NN * HEADS];
__device__ int    d_cnt[NN];          // zero-init; count fills, fill drains to 0
__device__ int    d_off[NN + 1];      // CSR offsets
__device__ int    d_bsum[SCAN_BLKS];  // scan block partials
__device__ int    d_src_csr[EN];      // src node per CSR slot
__device__ int    d_is64;

// -------- helpers --------
__device__ __forceinline__ void load_edge(const void* ei, int is64, int tid,
                                          int& s, int& d) {
    if (tid < EE) {
        if (is64) {
            const long long* p = (const long long*)ei;
            s = (int)p[tid];
            d = (int)p[EE + tid];
        } else {
            const int* p = (const int*)ei;
            s = p[tid];
            d = p[EE + tid];
        }
    } else {
        s = d = tid - EE;
    }
}

// -------- setup: detect int64 vs int32 edge_index --------
__global__ void setup_kernel(const int* ei) {
    if (threadIdx.x == 0) {
        int ok64 = 1;
        for (int i = 1; i < 256; i += 2)
            if (ei[i] != 0) { ok64 = 0; break; }
        d_is64 = ok64;
    }
}

__global__ void count_kernel(const void* __restrict__ ei) {
    int tid = blockIdx.x * blockDim.x + threadIdx.x;
    if (tid >= EN) return;
    int s, d;
    load_edge(ei, d_is64, tid, s, d);
    atomicAdd(&d_cnt[d], 1);
}

// -------- 3-phase exclusive scan of d_cnt -> d_off --------
__global__ void scanA_kernel() {
    __shared__ int sh[256];
    const int t = threadIdx.x;
    const int idx = blockIdx.x * 256 + t;
    int v = (idx < NN) ? d_cnt[idx] : 0;
    sh[t] = v;
    __syncthreads();
    #pragma unroll
    for (int o = 1; o < 256; o <<= 1) {
        int u = (t >= o) ? sh[t - o] : 0;
        __syncthreads();
        sh[t] += u;
        __syncthreads();
    }
    if (idx < NN) d_off[idx] = sh[t] - v;      // local exclusive
    if (t == 255) d_bsum[blockIdx.x] = sh[255];
}

__global__ void scanB_kernel() {    // 1 block, 64 threads
    __shared__ int sh[64];
    const int t = threadIdx.x;
    int v = (t < SCAN_BLKS) ? d_bsum[t] : 0;
    sh[t] = v;
    __syncthreads();
    #pragma unroll
    for (int o = 1; o < 64; o <<= 1) {
        int u = (t >= o) ? sh[t - o] : 0;
        __syncthreads();
        sh[t] += u;
        __syncthreads();
    }
    if (t < SCAN_BLKS) d_bsum[t] = sh[t] - v;  // exclusive block offsets
    if (t == 63) d_off[NN] = sh[63];           // total (= EN)
}

__global__ void scanC_kernel() {
    int idx = blockIdx.x * 256 + threadIdx.x;
    if (idx < NN) d_off[idx] += d_bsum[blockIdx.x];
}

// fill drains d_cnt back to 0 (atomicSub) -> no re-zeroing needed per run
__global__ void fill_kernel(const void* __restrict__ ei) {
    int tid = blockIdx.x * blockDim.x + threadIdx.x;
    if (tid >= EN) return;
    int s, d;
    load_edge(ei, d_is64, tid, s, d);
    int pos = atomicSub(&d_cnt[d], 1) - 1;     // slot in [0, deg)
    d_src_csr[d_off[d] + pos] = s;
}

// -------- double-buffered fp32 GEMM: C = A@B (+bias)(+relu) --------
// BM=64, BN=64, BK=16, 256 threads, 4x4 micro. C (fp32) and/or C16 (fp16).
__global__ void __launch_bounds__(256) gemm_bias_act(
        const float* __restrict__ A, const float* __restrict__ B,
        const float* __restrict__ bias, float* __restrict__ C,
        __half* __restrict__ C16, int M, int Nc, int K, int do_relu) {
    __shared__ float As[2][64][17];
    __shared__ float Bs[2][16][68];

    const int t  = threadIdx.x;
    const int tx = t & 15;
    const int ty = t >> 4;
    const int m0 = blockIdx.y * 64;
    const int n0 = blockIdx.x * 64;

    const int aRow = t >> 2;
    const int aCol = (t & 3) * 4;
    const int bRow = t >> 4;
    const int bCol = (t & 15) * 4;
    const bool aOk = (m0 + aRow < M);
    const int  nt  = K / 16;

    float4 av, bv;
    // preload tile 0
    av = aOk ? *(const float4*)&A[(size_t)(m0 + aRow) * K + aCol]
             : make_float4(0.f, 0.f, 0.f, 0.f);
    bv = *(const float4*)&B[(size_t)bRow * Nc + n0 + bCol];
    As[0][aRow][aCol + 0] = av.x; As[0][aRow][aCol + 1] = av.y;
    As[0][aRow][aCol + 2] = av.z; As[0][aRow][aCol + 3] = av.w;
    Bs[0][bRow][bCol + 0] = bv.x; Bs[0][bRow][bCol + 1] = bv.y;
    Bs[0][bRow][bCol + 2] = bv.z; Bs[0][bRow][bCol + 3] = bv.w;
    __syncthreads();

    float acc[4][4] = {};

    for (int tile = 0; tile < nt; tile++) {
        const int cur = tile & 1, nxt = cur ^ 1;
        if (tile + 1 < nt) {
            const int k0 = (tile + 1) * 16;
            av = aOk ? *(const float4*)&A[(size_t)(m0 + aRow) * K + k0 + aCol]
                     : make_float4(0.f, 0.f, 0.f, 0.f);
            bv = *(const float4*)&B[(size_t)(k0 + bRow) * Nc + n0 + bCol];
        }

        #pragma unroll
        for (int k = 0; k < 16; k++) {
            float a[4], b[4];
            #pragma unroll
            for (int i = 0; i < 4; i++) a[i] = As[cur][ty * 4 + i][k];
            #pragma unroll
            for (int j = 0; j < 4; j++) b[j] = Bs[cur][k][tx * 4 + j];
            #pragma unroll
            for (int i = 0; i < 4; i++)
                #pragma unroll
                for (int j = 0; j < 4; j++)
                    acc[i][j] = fmaf(a[i], b[j], acc[i][j]);
        }

        if (tile + 1 < nt) {
            As[nxt][aRow][aCol + 0] = av.x; As[nxt][aRow][aCol + 1] = av.y;
            As[nxt][aRow][aCol + 2] = av.z; As[nxt][aRow][aCol + 3] = av.w;
            Bs[nxt][bRow][bCol + 0] = bv.x; Bs[nxt][bRow][bCol + 1] = bv.y;
            Bs[nxt][bRow][bCol + 2] = bv.z; Bs[nxt][bRow][bCol + 3] = bv.w;
        }
        __syncthreads();
    }

    #pragma unroll
    for (int i = 0; i < 4; i++) {
        int row = m0 + ty * 4 + i;
        if (row >= M) continue;
        float o[4];
        #pragma unroll
        for (int j = 0; j < 4; j++) {
            float v = acc[i][j];
            if (bias) v += bias[n0 + tx * 4 + j];
            if (do_relu) v = fmaxf(v, 0.f);
            o[j] = v;
        }
        if (C)
            *(float4*)&C[(size_t)row * Nc + n0 + tx * 4] =
                make_float4(o[0], o[1], o[2], o[3]);
        if (C16) {
            __half2* hp = (__half2*)&C16[(size_t)row * Nc + n0 + tx * 4];
            hp[0] = __floats2half2_rn(o[0], o[1]);
            hp[1] = __floats2half2_rn(o[2], o[3]);
        }
    }
}

// -------- attention coefficients from fp16 g: one warp per (node, head) ----
// GC = 64 -> exactly one half2 per lane.
__global__ void attn_coef_kernel(const float* __restrict__ att_src,
                                 const float* __restrict__ att_dst) {
    int warp = (blockIdx.x * blockDim.x + threadIdx.x) >> 5;
    int lane = threadIdx.x & 31;
    if (warp >= NN * HEADS) return;
    int n = warp / HEADS, h = warp % HEADS;
    const __half2* gp = (const __half2*)(d_g16 + (size_t)n * FEAT + h * GC);
    float2 gv = __half22float2(gp[lane]);
    float as0 = att_src[h * GC + 2 * lane], as1 = att_src[h * GC + 2 * lane + 1];
    float ad0 = att_dst[h * GC + 2 * lane], ad1 = att_dst[h * GC + 2 * lane + 1];
    float ss = gv.x * as0 + gv.y * as1;
    float sd = gv.x * ad0 + gv.y * ad1;
    #pragma unroll
    for (int o = 16; o; o >>= 1) {
        ss += __shfl_xor_sync(0xFFFFFFFFu, ss, o);
        sd += __shfl_xor_sync(0xFFFFFFFFu, sd, o);
    }
    if (lane == 0) {
        d_asrc[n * HEADS + h] = ss;
        d_adst[n * HEADS + h] = sd;
    }
}

// -------- gather aggregation: two-pass, fp16 features in pass 2 --------
__global__ void __launch_bounds__(256) gather_kernel(float* __restrict__ out,
                                                     const float* __restrict__ bias_g) {
    __shared__ float s_ex[4][MAXDEG * HEADS];
    __shared__ int   s_src[4][MAXDEG];

    const int grp  = threadIdx.x >> 6;       // node slot in block
    const int t    = threadIdx.x & 63;       // channel quad owner
    const int node = blockIdx.x * 4 + grp;   // NN % 4 == 0
    const int h    = t >> 4;                 // head of my channels
    const int l16  = t & 15;

    const int beg = d_off[node];
    const int deg = d_off[node + 1] - beg;
    const int cached = (deg < MAXDEG) ? deg : MAXDEG;

    for (int j = t; j < cached; j += 64)
        s_src[grp][j] = d_src_csr[beg + j];
    __syncthreads();

    const float adst_h = d_adst[node * HEADS + h];

    // pass 1: ex per (edge, my head), partial softmax sum over 16 lanes
    float psum = 0.f;
    for (int j = l16; j < deg; j += 16) {
        int s = (j < MAXDEG) ? s_src[grp][j] : d_src_csr[beg + j];
        float e = d_asrc[s * HEADS + h] + adst_h;
        e = (e > 0.f) ? e : NEG_SLOPE * e;
        float ex = __expf(e);
        if (j < MAXDEG) s_ex[grp][j * HEADS + h] = ex;
        psum += ex;
    }
    #pragma unroll
    for (int o = 8; o; o >>= 1)
        psum += __shfl_xor_sync(0xFFFFFFFFu, psum, o);
    const float inv = __frcp_rn(psum);       // deg >= 1 (self loop)
    __syncthreads();

    // pass 2a: cached edges — unrolled, fp16 features (8B/edge/thread)
    float4 acc = make_float4(0.f, 0.f, 0.f, 0.f);
    #pragma unroll 8
    for (int j = 0; j < cached; j++) {
        float alpha = s_ex[grp][j * HEADS + h] * inv;
        int s = s_src[grp][j];
        const __half2* gp = (const __half2*)&d_g16[(size_t)s * FEAT + 4 * t];
        float2 f01 = __half22float2(gp[0]);
        float2 f23 = __half22float2(gp[1]);
        acc.x = fmaf(f01.x, alpha, acc.x);
        acc.y = fmaf(f01.y, alpha, acc.y);
        acc.z = fmaf(f23.x, alpha, acc.z);
        acc.w = fmaf(f23.y, alpha, acc.w);
    }
    // pass 2b: spill edges (deg > MAXDEG, rare)
    for (int j = cached; j < deg; j++) {
        int s = d_src_csr[beg + j];
        float e = d_asrc[s * HEADS + h] + adst_h;
        e = (e > 0.f) ? e : NEG_SLOPE * e;
        float alpha = __expf(e) * inv;
        const __half2* gp = (const __half2*)&d_g16[(size_t)s * FEAT + 4 * t];
        float2 f01 = __half22float2(gp[0]);
        float2 f23 = __half22float2(gp[1]);
        acc.x = fmaf(f01.x, alpha, acc.x);
        acc.y = fmaf(f01.y, alpha, acc.y);
        acc.z = fmaf(f23.x, alpha, acc.z);
        acc.w = fmaf(f23.y, alpha, acc.w);
    }

    float4 bv = *(const float4*)&bias_g[4 * t];
    acc.x += bv.x; acc.y += bv.y; acc.z += bv.z; acc.w += bv.w;
    *(float4*)&out[(size_t)node * FEAT + 4 * t] = acc;
}

// ----------------------------------------------------------------------------
extern "C" void kernel_launch(void* const* d_in, const int* in_sizes, int n_in,
                              void* d_out, int out_size) {
    const float* x        = (const float*)d_in[0];
    const void*  ei       = d_in[1];
    const float* W1       = (const float*)d_in[2];
    const float* b1       = (const float*)d_in[3];
    const float* W2       = (const float*)d_in[4];
    const float* b2       = (const float*)d_in[5];
    const float* Wg       = (const float*)d_in[6];
    const float* att_src  = (const float*)d_in[7];
    const float* att_dst  = (const float*)d_in[8];
    const float* bias_g   = (const float*)d_in[9];
    float* out = (float*)d_out;

    void *p_h1, *p_h2, *p_g16;
    cudaGetSymbolAddress(&p_h1, d_h1);
    cudaGetSymbolAddress(&p_h2, d_h2);
    cudaGetSymbolAddress(&p_g16, d_g16);

    // Launch order matters for ncu: profiled launch is index 3 -> GEMM1.
    setup_kernel<<<1, 32>>>((const int*)ei);                 // 0
    count_kernel<<<(EN + 255) / 256, 256>>>(ei);             // 1
    scanA_kernel<<<SCAN_BLKS, 256>>>();                      // 2
    {                                                        // 3 (profiled)
        dim3 grid(HIDD / 64, (NN + 63) / 64);
        gemm_bias_act<<<grid, 256>>>(x, W1, b1, (float*)p_h1, nullptr,
                                     NN, HIDD, IND, 1);
    }
    scanB_kernel<<<1, 64>>>();                               // 4
    scanC_kernel<<<SCAN_BLKS, 256>>>();                      // 5
    fill_kernel<<<(EN + 255) / 256, 256>>>(ei);              // 6
    {                                                        // 7
        dim3 grid(OUTD / 64, (NN + 63) / 64);
        gemm_bias_act<<<grid, 256>>>((const float*)p_h1, W2, b2, (float*)p_h2,
                                     nullptr, NN, OUTD, HIDD, 0);
    }
    {                                                        // 8: fp16-only out
        dim3 grid(FEAT / 64, (NN + 63) / 64);
        gemm_bias_act<<<grid, 256>>>((const float*)p_h2, Wg, nullptr, nullptr,
                                     (__half*)p_g16, NN, FEAT, OUTD, 0);
    }
    {                                                        // 9
        int warps = NN * HEADS;
        attn_coef_kernel<<<(warps * 32 + 255) / 256, 256>>>(att_src, att_dst);
    }
    gather_kernel<<<NN / 4, 256>>>(out, bias_g);             // 10
}

// round 10
// speedup vs baseline: 1.2382x; 1.2382x over previous
#include <cuda_runtime.h>
#include <cuda_fp16.h>
#include <mma.h>
#include <math.h>

using namespace nvcuda;

// Problem constants
static constexpr int NN   = 10000;
static constexpr int EE   = 320000;
static constexpr int EN   = EE + NN;        // edges + self loops
static constexpr int IND  = 512;
static constexpr int HIDD = 128;
static constexpr int OUTD = 128;
static constexpr int HEADS = 4;
static constexpr int GC    = 64;
static constexpr int FEAT  = HEADS * GC;    // 256
static constexpr float NEG_SLOPE = 0.2f;
static constexpr int MAXDEG = 256;
static constexpr int SCAN_BLKS = 40;

// -------- scratch (device globals: no allocation allowed) --------
__device__ __half d_xh [(size_t)NN * IND];
__device__ __half d_xl [(size_t)NN * IND];
__device__ __half d_w1h[IND * HIDD];
__device__ __half d_w1l[IND * HIDD];
__device__ __half d_w2h[HIDD * OUTD];
__device__ __half d_w2l[HIDD * OUTD];
__device__ __half d_wgh[OUTD * FEAT];
__device__ __half d_wgl[OUTD * FEAT];
__device__ __half d_h1h[(size_t)NN * HIDD];
__device__ __half d_h1l[(size_t)NN * HIDD];
__device__ __half d_h2h[(size_t)NN * OUTD];
__device__ __half d_h2l[(size_t)NN * OUTD];
__device__ __half d_g16[(size_t)NN * FEAT];
__device__ float  d_asrc[NN * HEADS];
__device__ float  d_adst[NN * HEADS];
__device__ int    d_cnt[NN];          // zero-init; count fills, fill drains to 0
__device__ int    d_off[NN + 1];
__device__ int    d_bsum[SCAN_BLKS];
__device__ int    d_src_csr[EN];
__device__ int    d_is64;

// -------- helpers --------
__device__ __forceinline__ void load_edge(const void* ei, int is64, int tid,
                                          int& s, int& d) {
    if (tid < EE) {
        if (is64) {
            const long long* p = (const long long*)ei;
            s = (int)p[tid];
            d = (int)p[EE + tid];
        } else {
            const int* p = (const int*)ei;
            s = p[tid];
            d = p[EE + tid];
        }
    } else {
        s = d = tid - EE;
    }
}

// -------- setup: detect int64 vs int32 edge_index --------
__global__ void setup_kernel(const int* ei) {
    if (threadIdx.x == 0) {
        int ok64 = 1;
        for (int i = 1; i < 256; i += 2)
            if (ei[i] != 0) { ok64 = 0; break; }
        d_is64 = ok64;
    }
}

// -------- split fp32 -> (hi, lo) fp16 pair;  n % 4 == 0 --------
__global__ void convert_split_kernel(const float* __restrict__ src,
                                     __half* __restrict__ hi,
                                     __half* __restrict__ lo, int n4) {
    int i = blockIdx.x * blockDim.x + threadIdx.x;
    if (i >= n4) return;
    float4 v = ((const float4*)src)[i];
    __half h0 = __float2half_rn(v.x), h1 = __float2half_rn(v.y);
    __half h2 = __float2half_rn(v.z), h3 = __float2half_rn(v.w);
    __half l0 = __float2half_rn(v.x - __half2float(h0));
    __half l1 = __float2half_rn(v.y - __half2float(h1));
    __half l2 = __float2half_rn(v.z - __half2float(h2));
    __half l3 = __float2half_rn(v.w - __half2float(h3));
    ((__half2*)hi)[2 * i]     = __halves2half2(h0, h1);
    ((__half2*)hi)[2 * i + 1] = __halves2half2(h2, h3);
    ((__half2*)lo)[2 * i]     = __halves2half2(l0, l1);
    ((__half2*)lo)[2 * i + 1] = __halves2half2(l2, l3);
}

// -------- CSR build --------
__global__ void count_kernel(const void* __restrict__ ei) {
    int tid = blockIdx.x * blockDim.x + threadIdx.x;
    if (tid >= EN) return;
    int s, d;
    load_edge(ei, d_is64, tid, s, d);
    atomicAdd(&d_cnt[d], 1);
}

__global__ void scanA_kernel() {
    __shared__ int sh[256];
    const int t = threadIdx.x;
    const int idx = blockIdx.x * 256 + t;
    int v = (idx < NN) ? d_cnt[idx] : 0;
    sh[t] = v;
    __syncthreads();
    #pragma unroll
    for (int o = 1; o < 256; o <<= 1) {
        int u = (t >= o) ? sh[t - o] : 0;
        __syncthreads();
        sh[t] += u;
        __syncthreads();
    }
    if (idx < NN) d_off[idx] = sh[t] - v;
    if (t == 255) d_bsum[blockIdx.x] = sh[255];
}

__global__ void scanB_kernel() {
    __shared__ int sh[64];
    const int t = threadIdx.x;
    int v = (t < SCAN_BLKS) ? d_bsum[t] : 0;
    sh[t] = v;
    __syncthreads();
    #pragma unroll
    for (int o = 1; o < 64; o <<= 1) {
        int u = (t >= o) ? sh[t - o] : 0;
        __syncthreads();
        sh[t] += u;
        __syncthreads();
    }
    if (t < SCAN_BLKS) d_bsum[t] = sh[t] - v;
    if (t == 63) d_off[NN] = sh[63];
}

__global__ void scanC_kernel() {
    int idx = blockIdx.x * 256 + threadIdx.x;
    if (idx < NN) d_off[idx] += d_bsum[blockIdx.x];
}

__global__ void fill_kernel(const void* __restrict__ ei) {
    int tid = blockIdx.x * blockDim.x + threadIdx.x;
    if (tid >= EN) return;
    int s, d;
    load_edge(ei, d_is64, tid, s, d);
    int pos = atomicSub(&d_cnt[d], 1) - 1;
    d_src_csr[d_off[d] + pos] = s;
}

// -------- split-fp16 tensor-core GEMM --------
// C = (Ahi+Alo)@(Bhi+Blo) approx = Ahi@Bhi + Ahi@Blo + Alo@Bhi (fp32 acc).
// A: [M,K] row-major fp16 pair; B: [K,N] row-major fp16 pair.
// Epilogue: +bias (fp32), optional relu, write hi (+ optional lo) fp16.
// Tile: BM=64, BN=64, BK=32. 256 threads = 8 warps (2x4 warp grid).
static constexpr int LDA_S = 40;   // 32 + 8 pad (halfs)
static constexpr int LDB_S = 72;   // 64 + 8 pad (halfs)
static constexpr int LDC_S = 68;   // 64 + 4 pad (floats)

__global__ void __launch_bounds__(256) gemm_wmma(
        const __half* __restrict__ Ah, const __half* __restrict__ Al,
        const __half* __restrict__ Bh, const __half* __restrict__ Bl,
        const float* __restrict__ bias,
        __half* __restrict__ Oh, __half* __restrict__ Ol,
        int M, int N, int K, int do_relu) {
    __shared__ __align__(16) char sm[19456];
    __half* Ash = (__half*)sm;                    // 64*40 = 2560 halfs
    __half* Asl = Ash + 64 * LDA_S;               // 2560
    __half* Bsh = (__half*)(sm + 10240);          // 32*72 = 2304 halfs
    __half* Bsl = Bsh + 32 * LDB_S;
    float*  Cf  = (float*)sm;                     // 64*68 floats (reused)

    const int t  = threadIdx.x;
    const int wid = t >> 5;
    const int wm = wid >> 2;          // 0..1
    const int wn = wid & 3;           // 0..3
    const int m0 = blockIdx.y * 64;
    const int n0 = blockIdx.x * 64;

    // A tile loader: 64 rows x 32 cols, 8 halfs/thread
    const int ar = t >> 2;
    const int ac = (t & 3) * 8;
    // B tile loader: 32 rows x 64 cols, 8 halfs/thread
    const int br = t >> 3;
    const int bc = (t & 7) * 8;
    const bool aOk = (m0 + ar < M);

    wmma::fragment<wmma::accumulator, 16, 16, 16, float> acc[2];
    wmma::fill_fragment(acc[0], 0.f);
    wmma::fill_fragment(acc[1], 0.f);

    const uint4 zero4 = make_uint4(0, 0, 0, 0);

    for (int k0 = 0; k0 < K; k0 += 32) {
        uint4 vah = zero4, val = zero4;
        if (aOk) {
            vah = *(const uint4*)&Ah[(size_t)(m0 + ar) * K + k0 + ac];
            val = *(const uint4*)&Al[(size_t)(m0 + ar) * K + k0 + ac];
        }
        uint4 vbh = *(const uint4*)&Bh[(size_t)(k0 + br) * N + n0 + bc];
        uint4 vbl = *(const uint4*)&Bl[(size_t)(k0 + br) * N + n0 + bc];
        *(uint4*)&Ash[ar * LDA_S + ac] = vah;
        *(uint4*)&Asl[ar * LDA_S + ac] = val;
        *(uint4*)&Bsh[br * LDB_S + bc] = vbh;
        *(uint4*)&Bsl[br * LDB_S + bc] = vbl;
        __syncthreads();

        #pragma unroll
        for (int kk = 0; kk < 32; kk += 16) {
            wmma::fragment<wmma::matrix_b, 16, 16, 16, __half, wmma::row_major> bfh, bfl;
            wmma::load_matrix_sync(bfh, &Bsh[kk * LDB_S + wn * 16], LDB_S);
            wmma::load_matrix_sync(bfl, &Bsl[kk * LDB_S + wn * 16], LDB_S);
            #pragma unroll
            for (int i = 0; i < 2; i++) {
                wmma::fragment<wmma::matrix_a, 16, 16, 16, __half, wmma::row_major> afh, afl;
                const int ro = (wm * 32 + i * 16) * LDA_S + kk;
                wmma::load_matrix_sync(afh, &Ash[ro], LDA_S);
                wmma::load_matrix_sync(afl, &Asl[ro], LDA_S);
                wmma::mma_sync(acc[i], afh, bfh, acc[i]);
                wmma::mma_sync(acc[i], afh, bfl, acc[i]);
                wmma::mma_sync(acc[i], afl, bfh, acc[i]);
            }
        }
        __syncthreads();
    }

    // stage fp32 results to smem
    wmma::store_matrix_sync(&Cf[(wm * 32) * LDC_S + wn * 16], acc[0], LDC_S,
                            wmma::mem_row_major);
    wmma::store_matrix_sync(&Cf[(wm * 32 + 16) * LDC_S + wn * 16], acc[1], LDC_S,
                            wmma::mem_row_major);
    __syncthreads();

    // epilogue: each thread handles one row-quarter (16 cols)
    {
        const int row = t >> 2;
        const int cb  = (t & 3) * 16;
        if (m0 + row < M) {
            #pragma unroll
            for (int jj = 0; jj < 8; jj++) {
                float v0 = Cf[row * LDC_S + cb + 2 * jj];
                float v1 = Cf[row * LDC_S + cb + 2 * jj + 1];
                if (bias) {
                    v0 += bias[n0 + cb + 2 * jj];
                    v1 += bias[n0 + cb + 2 * jj + 1];
                }
                if (do_relu) { v0 = fmaxf(v0, 0.f); v1 = fmaxf(v1, 0.f); }
                __half h0 = __float2half_rn(v0), h1 = __float2half_rn(v1);
                size_t o = (size_t)(m0 + row) * N + n0 + cb + 2 * jj;
                *(__half2*)&Oh[o] = __halves2half2(h0, h1);
                if (Ol) {
                    __half l0 = __float2half_rn(v0 - __half2float(h0));
                    __half l1 = __float2half_rn(v1 - __half2float(h1));
                    *(__half2*)&Ol[o] = __halves2half2(l0, l1);
                }
            }
        }
    }
}

// -------- attention coefficients from fp16 g: one warp per (node, head) ----
__global__ void attn_coef_kernel(const float* __restrict__ att_src,
                                 const float* __restrict__ att_dst) {
    int warp = (blockIdx.x * blockDim.x + threadIdx.x) >> 5;
    int lane = threadIdx.x & 31;
    if (warp >= NN * HEADS) return;
    int n = warp / HEADS, h = warp % HEADS;
    const __half2* gp = (const __half2*)(d_g16 + (size_t)n * FEAT + h * GC);
    float2 gv = __half22float2(gp[lane]);
    float ss = gv.x * att_src[h * GC + 2 * lane] +
               gv.y * att_src[h * GC + 2 * lane + 1];
    float sd = gv.x * att_dst[h * GC + 2 * lane] +
               gv.y * att_dst[h * GC + 2 * lane + 1];
    #pragma unroll
    for (int o = 16; o; o >>= 1) {
        ss += __shfl_xor_sync(0xFFFFFFFFu, ss, o);
        sd += __shfl_xor_sync(0xFFFFFFFFu, sd, o);
    }
    if (lane == 0) {
        d_asrc[n * HEADS + h] = ss;
        d_adst[n * HEADS + h] = sd;
    }
}

// -------- gather aggregation: two-pass, fp16 features in pass 2 --------
__global__ void __launch_bounds__(256) gather_kernel(float* __restrict__ out,
                                                     const float* __restrict__ bias_g) {
    __shared__ float s_ex[4][MAXDEG * HEADS];
    __shared__ int   s_src[4][MAXDEG];

    const int grp  = threadIdx.x >> 6;
    const int t    = threadIdx.x & 63;
    const int node = blockIdx.x * 4 + grp;
    const int h    = t >> 4;
    const int l16  = t & 15;

    const int beg = d_off[node];
    const int deg = d_off[node + 1] - beg;
    const int cached = (deg < MAXDEG) ? deg : MAXDEG;

    for (int j = t; j < cached; j += 64)
        s_src[grp][j] = d_src_csr[beg + j];
    __syncthreads();

    const float adst_h = d_adst[node * HEADS + h];

    float psum = 0.f;
    for (int j = l16; j < deg; j += 16) {
        int s = (j < MAXDEG) ? s_src[grp][j] : d_src_csr[beg + j];
        float e = d_asrc[s * HEADS + h] + adst_h;
        e = (e > 0.f) ? e : NEG_SLOPE * e;
        float ex = __expf(e);
        if (j < MAXDEG) s_ex[grp][j * HEADS + h] = ex;
        psum += ex;
    }
    #pragma unroll
    for (int o = 8; o; o >>= 1)
        psum += __shfl_xor_sync(0xFFFFFFFFu, psum, o);
    const float inv = __frcp_rn(psum);
    __syncthreads();

    float4 acc = make_float4(0.f, 0.f, 0.f, 0.f);
    #pragma unroll 8
    for (int j = 0; j < cached; j++) {
        float alpha = s_ex[grp][j * HEADS + h] * inv;
        int s = s_src[grp][j];
        const __half2* gp = (const __half2*)&d_g16[(size_t)s * FEAT + 4 * t];
        float2 f01 = __half22float2(gp[0]);
        float2 f23 = __half22float2(gp[1]);
        acc.x = fmaf(f01.x, alpha, acc.x);
        acc.y = fmaf(f01.y, alpha, acc.y);
        acc.z = fmaf(f23.x, alpha, acc.z);
        acc.w = fmaf(f23.y, alpha, acc.w);
    }
    for (int j = cached; j < deg; j++) {
        int s = d_src_csr[beg + j];
        float e = d_asrc[s * HEADS + h] + adst_h;
        e = (e > 0.f) ? e : NEG_SLOPE * e;
        float alpha = __expf(e) * inv;
        const __half2* gp = (const __half2*)&d_g16[(size_t)s * FEAT + 4 * t];
        float2 f01 = __half22float2(gp[0]);
        float2 f23 = __half22float2(gp[1]);
        acc.x = fmaf(f01.x, alpha, acc.x);
        acc.y = fmaf(f01.y, alpha, acc.y);
        acc.z = fmaf(f23.x, alpha, acc.z);
        acc.w = fmaf(f23.y, alpha, acc.w);
    }

    float4 bv = *(const float4*)&bias_g[4 * t];
    acc.x += bv.x; acc.y += bv.y; acc.z += bv.z; acc.w += bv.w;
    *(float4*)&out[(size_t)node * FEAT + 4 * t] = acc;
}

// ----------------------------------------------------------------------------
extern "C" void kernel_launch(void* const* d_in, const int* in_sizes, int n_in,
                              void* d_out, int out_size) {
    const float* x        = (const float*)d_in[0];
    const void*  ei       = d_in[1];
    const float* W1       = (const float*)d_in[2];
    const float* b1       = (const float*)d_in[3];
    const float* W2       = (const float*)d_in[4];
    const float* b2       = (const float*)d_in[5];
    const float* Wg       = (const float*)d_in[6];
    const float* att_src  = (const float*)d_in[7];
    const float* att_dst  = (const float*)d_in[8];
    const float* bias_g   = (const float*)d_in[9];
    float* out = (float*)d_out;

    void *p_xh, *p_xl, *p_w1h, *p_w1l, *p_w2h, *p_w2l, *p_wgh, *p_wgl;
    void *p_h1h, *p_h1l, *p_h2h, *p_h2l, *p_g16;
    cudaGetSymbolAddress(&p_xh, d_xh);   cudaGetSymbolAddress(&p_xl, d_xl);
    cudaGetSymbolAddress(&p_w1h, d_w1h); cudaGetSymbolAddress(&p_w1l, d_w1l);
    cudaGetSymbolAddress(&p_w2h, d_w2h); cudaGetSymbolAddress(&p_w2l, d_w2l);
    cudaGetSymbolAddress(&p_wgh, d_wgh); cudaGetSymbolAddress(&p_wgl, d_wgl);
    cudaGetSymbolAddress(&p_h1h, d_h1h); cudaGetSymbolAddress(&p_h1l, d_h1l);
    cudaGetSymbolAddress(&p_h2h, d_h2h); cudaGetSymbolAddress(&p_h2l, d_h2l);
    cudaGetSymbolAddress(&p_g16, d_g16);

    setup_kernel<<<1, 32>>>((const int*)ei);                             // 0
    {   // 1: split-convert x
        int n4 = NN * IND / 4;
        convert_split_kernel<<<(n4 + 255) / 256, 256>>>(
            x, (__half*)p_xh, (__half*)p_xl, n4);
    }
    {   // 2: split-convert W1
        int n4 = IND * HIDD / 4;
        convert_split_kernel<<<(n4 + 255) / 256, 256>>>(
            W1, (__half*)p_w1h, (__half*)p_w1l, n4);
    }
    {   // 3 (profiled): GEMM1  h1 = relu(x@W1 + b1)
        dim3 grid(HIDD / 64, (NN + 63) / 64);
        gemm_wmma<<<grid, 256>>>((const __half*)p_xh, (const __half*)p_xl,
                                 (const __half*)p_w1h, (const __half*)p_w1l,
                                 b1, (__half*)p_h1h, (__half*)p_h1l,
                                 NN, HIDD, IND, 1);
    }
    {   // 4: split-convert W2
        int n4 = HIDD * OUTD / 4;
        convert_split_kernel<<<(n4 + 255) / 256, 256>>>(
            W2, (__half*)p_w2h, (__half*)p_w2l, n4);
    }
    {   // 5: split-convert Wg
        int n4 = OUTD * FEAT / 4;
        convert_split_kernel<<<(n4 + 255) / 256, 256>>>(
            Wg, (__half*)p_wgh, (__half*)p_wgl, n4);
    }
    count_kernel<<<(EN + 255) / 256, 256>>>(ei);                         // 6
    scanA_kernel<<<SCAN_BLKS, 256>>>();                                  // 7
    scanB_kernel<<<1, 64>>>();                                           // 8
    scanC_kernel<<<SCAN_BLKS, 256>>>();                                  // 9
    fill_kernel<<<(EN + 255) / 256, 256>>>(ei);                          // 10
    {   // 11: GEMM2  h2 = h1@W2 + b2
        dim3 grid(OUTD / 64, (NN + 63) / 64);
        gemm_wmma<<<grid, 256>>>((const __half*)p_h1h, (const __half*)p_h1l,
                                 (const __half*)p_w2h, (const __half*)p_w2l,
                                 b2, (__half*)p_h2h, (__half*)p_h2l,
                                 NN, OUTD, HIDD, 0);
    }
    {   // 12: GEMM3  g = h2@Wg  (hi only out)
        dim3 grid(FEAT / 64, (NN + 63) / 64);
        gemm_wmma<<<grid, 256>>>((const __half*)p_h2h, (const __half*)p_h2l,
                                 (const __half*)p_wgh, (const __half*)p_wgl,
                                 nullptr, (__half*)p_g16, nullptr,
                                 NN, FEAT, OUTD, 0);
    }
    {   // 13
        int warps = NN * HEADS;
        attn_coef_kernel<<<(warps * 32 + 255) / 256, 256>>>(att_src, att_dst);
    }
    gather_kernel<<<NN / 4, 256>>>(out, bias_g);                         // 14
}